// round 2
// baseline (speedup 1.0000x reference)
#include <cuda_runtime.h>
#include <cuda_bf16.h>

#define BATCH      256
#define INPUT_DIM  4096
#define SOMA       2048
#define BRANCH     16
#define NUM_DEND   (SOMA * BRANCH)   // 32768
#define SAMPLE     32
#define NEG        0.1f

#define BT         4                 // batches per block (one float4 per x element)
#define DT         512               // dendrites per block (= threads)
#define NTHREADS   512

// smem: xs[4096] float4 (batches b0..b0+3 interleaved) = 64KB  -> 2 CTAs/SM
__global__ __launch_bounds__(NTHREADS, 2)
void dend_kernel(const float* __restrict__ x,
                 const int*   __restrict__ idx,
                 const float* __restrict__ sw,
                 const float* __restrict__ sb,
                 const float* __restrict__ cw,
                 const float* __restrict__ somab,
                 float* __restrict__ soma_out,
                 float* __restrict__ dend_out)
{
    extern __shared__ float4 xs[];

    const int b0  = blockIdx.y * BT;
    const int d0  = blockIdx.x * DT;
    const int tid = threadIdx.x;

    // Stage 4 x rows into smem, batch-interleaved
    const float* xr = x + (size_t)b0 * INPUT_DIM;
    for (int i = tid; i < INPUT_DIM; i += NTHREADS) {
        float4 v;
        v.x = xr[0 * INPUT_DIM + i];
        v.y = xr[1 * INPUT_DIM + i];
        v.z = xr[2 * INPUT_DIM + i];
        v.w = xr[3 * INPUT_DIM + i];
        xs[i] = v;
    }
    __syncthreads();

    const int d = d0 + tid;
    const int4*   idx4 = (const int4*)  (idx + (size_t)d * SAMPLE);
    const float4* wv4  = (const float4*)(sw  + (size_t)d * SAMPLE);

    float acc0 = 0.f, acc1 = 0.f, acc2 = 0.f, acc3 = 0.f;

    #pragma unroll
    for (int s4 = 0; s4 < SAMPLE / 4; ++s4) {
        const int4   i4 = idx4[s4];
        const float4 wv = wv4[s4];

        {   const float4 a = xs[i4.x]; const float w = wv.x;
            acc0 = fmaf(w, a.x, acc0); acc1 = fmaf(w, a.y, acc1);
            acc2 = fmaf(w, a.z, acc2); acc3 = fmaf(w, a.w, acc3); }
        {   const float4 a = xs[i4.y]; const float w = wv.y;
            acc0 = fmaf(w, a.x, acc0); acc1 = fmaf(w, a.y, acc1);
            acc2 = fmaf(w, a.z, acc2); acc3 = fmaf(w, a.w, acc3); }
        {   const float4 a = xs[i4.z]; const float w = wv.z;
            acc0 = fmaf(w, a.x, acc0); acc1 = fmaf(w, a.y, acc1);
            acc2 = fmaf(w, a.z, acc2); acc3 = fmaf(w, a.w, acc3); }
        {   const float4 a = xs[i4.w]; const float w = wv.w;
            acc0 = fmaf(w, a.x, acc0); acc1 = fmaf(w, a.y, acc1);
            acc2 = fmaf(w, a.z, acc2); acc3 = fmaf(w, a.w, acc3); }
    }

    const float bias = sb[d];
    const float cwv  = cw[d];   // cable_weights flattened [soma][branch] == index d

    float sv[BT];
    float accs[BT] = {acc0, acc1, acc2, acc3};
    #pragma unroll
    for (int j = 0; j < BT; ++j) {
        float p = accs[j] + bias;
        float a = p >= 0.f ? p : NEG * p;
        dend_out[(size_t)(b0 + j) * NUM_DEND + d] = a;
        sv[j] = a * cwv;
    }

    // Segmented reduction over the 16 branches (16 consecutive lanes)
    #pragma unroll
    for (int off = 8; off >= 1; off >>= 1) {
        #pragma unroll
        for (int j = 0; j < BT; ++j)
            sv[j] += __shfl_xor_sync(0xffffffffu, sv[j], off);
    }

    if ((tid & (BRANCH - 1)) == 0) {
        const int n  = d >> 4;
        const float nb = somab[n];
        #pragma unroll
        for (int j = 0; j < BT; ++j) {
            float p = sv[j] + nb;
            soma_out[(size_t)(b0 + j) * SOMA + n] = p >= 0.f ? p : NEG * p;
        }
    }
}

extern "C" void kernel_launch(void* const* d_in, const int* in_sizes, int n_in,
                              void* d_out, int out_size)
{
    const float* x     = (const float*)d_in[0];
    const int*   idx   = (const int*)  d_in[1];
    const float* sw    = (const float*)d_in[2];
    const float* sb    = (const float*)d_in[3];
    const float* cw    = (const float*)d_in[4];
    const float* somab = (const float*)d_in[5];

    float* out      = (float*)d_out;
    float* soma_out = out;                          // [256, 2048]
    float* dend_out = out + (size_t)BATCH * SOMA;   // [256, 32768]

    const size_t smem = INPUT_DIM * sizeof(float4);  // 64 KB
    cudaFuncSetAttribute(dend_kernel, cudaFuncAttributeMaxDynamicSharedMemorySize, (int)smem);

    dim3 grid(NUM_DEND / DT, BATCH / BT);
    dend_kernel<<<grid, NTHREADS, smem>>>(x, idx, sw, sb, cw, somab, soma_out, dend_out);
}

// round 3
// speedup vs baseline: 3.0813x; 3.0813x over previous
#include <cuda_runtime.h>
#include <cuda_fp16.h>

#define BATCH      256
#define INPUT_DIM  4096
#define SOMA       2048
#define BRANCH     16
#define NUM_DEND   (SOMA * BRANCH)   // 32768
#define SAMPLE     32
#define NEG        0.1f

#define BT         8                 // batches per block (half2 x4 = 16B per x element)
#define NBG        (BATCH / BT)      // 32 batch groups
#define DT         512
#define NTHREADS   512

// Scratch (allocation-free rule: __device__ globals)
__device__ int4   g_idxT[(SAMPLE/4) * NUM_DEND];   // [s4][d]  4 MB
__device__ float4 g_swT [(SAMPLE/4) * NUM_DEND];   // [s4][d]  4 MB
__device__ uint4  g_xprep[NBG * INPUT_DIM];        // [bg][i]  8 batches as 4x half2, 2 MB

// ---- pre-pass 1: pack x into batch-interleaved fp16 ----
__global__ void prep_x(const float* __restrict__ x)
{
    int t = blockIdx.x * blockDim.x + threadIdx.x;   // 0 .. NBG*INPUT_DIM-1
    int bg = t / INPUT_DIM;
    int i  = t - bg * INPUT_DIM;
    const float* xr = x + (size_t)(bg * BT) * INPUT_DIM + i;
    __half2 h0 = __floats2half2_rn(xr[0 * INPUT_DIM], xr[1 * INPUT_DIM]);
    __half2 h1 = __floats2half2_rn(xr[2 * INPUT_DIM], xr[3 * INPUT_DIM]);
    __half2 h2 = __floats2half2_rn(xr[4 * INPUT_DIM], xr[5 * INPUT_DIM]);
    __half2 h3 = __floats2half2_rn(xr[6 * INPUT_DIM], xr[7 * INPUT_DIM]);
    uint4 v;
    v.x = *reinterpret_cast<unsigned*>(&h0);
    v.y = *reinterpret_cast<unsigned*>(&h1);
    v.z = *reinterpret_cast<unsigned*>(&h2);
    v.w = *reinterpret_cast<unsigned*>(&h3);
    g_xprep[t] = v;
}

// ---- pre-pass 2: transpose idx / sw to [s4][d] ----
__global__ void prep_idx(const int* __restrict__ idx, const float* __restrict__ sw)
{
    int d = blockIdx.x * blockDim.x + threadIdx.x;   // 0 .. NUM_DEND-1
    const int4*   ir = (const int4*)  (idx + (size_t)d * SAMPLE);
    const float4* wr = (const float4*)(sw  + (size_t)d * SAMPLE);
    #pragma unroll
    for (int s4 = 0; s4 < SAMPLE / 4; ++s4) {
        g_idxT[s4 * NUM_DEND + d] = ir[s4];
        g_swT [s4 * NUM_DEND + d] = wr[s4];
    }
}

// ---- main kernel ----
__global__ __launch_bounds__(NTHREADS, 2)
void dend_kernel(const float* __restrict__ sb,
                 const float* __restrict__ cw,
                 const float* __restrict__ somab,
                 float* __restrict__ soma_out,
                 float* __restrict__ dend_out)
{
    extern __shared__ uint4 xs[];   // [INPUT_DIM] = 64 KB

    const int bg  = blockIdx.y;
    const int b0  = bg * BT;
    const int d0  = blockIdx.x * DT;
    const int tid = threadIdx.x;

    // Stage packed x group (coalesced LDG.128 + STS.128)
    const uint4* xp = g_xprep + (size_t)bg * INPUT_DIM;
    for (int i = tid; i < INPUT_DIM; i += NTHREADS)
        xs[i] = xp[i];
    __syncthreads();

    const int d = d0 + tid;

    float acc0 = 0.f, acc1 = 0.f, acc2 = 0.f, acc3 = 0.f;
    float acc4 = 0.f, acc5 = 0.f, acc6 = 0.f, acc7 = 0.f;

    #pragma unroll
    for (int s4 = 0; s4 < SAMPLE / 4; ++s4) {
        const int4   i4 = g_idxT[s4 * NUM_DEND + d];   // coalesced
        const float4 wv = g_swT [s4 * NUM_DEND + d];   // coalesced

        #pragma unroll
        for (int q = 0; q < 4; ++q) {
            const int   ix = (q == 0) ? i4.x : (q == 1) ? i4.y : (q == 2) ? i4.z : i4.w;
            const float w  = (q == 0) ? wv.x : (q == 1) ? wv.y : (q == 2) ? wv.z : wv.w;
            const uint4 raw = xs[ix];
            float2 f0 = __half22float2(*reinterpret_cast<const __half2*>(&raw.x));
            float2 f1 = __half22float2(*reinterpret_cast<const __half2*>(&raw.y));
            float2 f2 = __half22float2(*reinterpret_cast<const __half2*>(&raw.z));
            float2 f3 = __half22float2(*reinterpret_cast<const __half2*>(&raw.w));
            acc0 = fmaf(w, f0.x, acc0); acc1 = fmaf(w, f0.y, acc1);
            acc2 = fmaf(w, f1.x, acc2); acc3 = fmaf(w, f1.y, acc3);
            acc4 = fmaf(w, f2.x, acc4); acc5 = fmaf(w, f2.y, acc5);
            acc6 = fmaf(w, f3.x, acc6); acc7 = fmaf(w, f3.y, acc7);
        }
    }

    const float bias = sb[d];
    const float cwv  = cw[d];   // cable_weights flattened [soma][branch] == index d

    float sv[BT];
    float accs[BT] = {acc0, acc1, acc2, acc3, acc4, acc5, acc6, acc7};
    #pragma unroll
    for (int j = 0; j < BT; ++j) {
        float p = accs[j] + bias;
        float a = p >= 0.f ? p : NEG * p;
        dend_out[(size_t)(b0 + j) * NUM_DEND + d] = a;
        sv[j] = a * cwv;
    }

    // Segmented reduction over 16 branches (16 consecutive lanes)
    #pragma unroll
    for (int off = 8; off >= 1; off >>= 1) {
        #pragma unroll
        for (int j = 0; j < BT; ++j)
            sv[j] += __shfl_xor_sync(0xffffffffu, sv[j], off);
    }

    if ((tid & (BRANCH - 1)) == 0) {
        const int n  = d >> 4;
        const float nb = somab[n];
        #pragma unroll
        for (int j = 0; j < BT; ++j) {
            float p = sv[j] + nb;
            soma_out[(size_t)(b0 + j) * SOMA + n] = p >= 0.f ? p : NEG * p;
        }
    }
}

extern "C" void kernel_launch(void* const* d_in, const int* in_sizes, int n_in,
                              void* d_out, int out_size)
{
    const float* x     = (const float*)d_in[0];
    const int*   idx   = (const int*)  d_in[1];
    const float* sw    = (const float*)d_in[2];
    const float* sb    = (const float*)d_in[3];
    const float* cw    = (const float*)d_in[4];
    const float* somab = (const float*)d_in[5];

    float* out      = (float*)d_out;
    float* soma_out = out;                          // [256, 2048]
    float* dend_out = out + (size_t)BATCH * SOMA;   // [256, 32768]

    prep_x  <<<(NBG * INPUT_DIM) / 256, 256>>>(x);
    prep_idx<<<NUM_DEND / 256, 256>>>(idx, sw);

    const size_t smem = INPUT_DIM * sizeof(uint4);  // 64 KB
    cudaFuncSetAttribute(dend_kernel, cudaFuncAttributeMaxDynamicSharedMemorySize, (int)smem);

    dim3 grid(NUM_DEND / DT, BATCH / BT);
    dend_kernel<<<grid, NTHREADS, smem>>>(sb, cw, somab, soma_out, dend_out);
}

// round 4
// speedup vs baseline: 3.2693x; 1.0610x over previous
#include <cuda_runtime.h>
#include <cuda_fp16.h>

#define BATCH      256
#define INPUT_DIM  4096
#define SOMA       2048
#define BRANCH     16
#define NUM_DEND   (SOMA * BRANCH)   // 32768
#define SAMPLE     32
#define NEG        0.1f

#define BT         8                 // batches per block (4x half2 = 16B per x element)
#define NBG        (BATCH / BT)      // 32 batch groups
#define DT         512
#define NTHREADS   512

// Scratch (allocation-free rule: __device__ globals)
__device__ uint4  g_pk[(SAMPLE/4) * NUM_DEND];     // [s4][d]: 4x {idx:u16, w:fp16}, 4 MB
__device__ uint4  g_xprep[NBG * INPUT_DIM];        // [bg][i]: 8 batches as 4x half2, 2 MB

// ---- pre-pass 1: pack x into batch-interleaved fp16 (2 threads per element) ----
__global__ void prep_x(const float* __restrict__ x)
{
    int t  = blockIdx.x * blockDim.x + threadIdx.x;  // 0 .. NBG*2*INPUT_DIM-1
    int bg = t / (2 * INPUT_DIM);
    int r  = t - bg * 2 * INPUT_DIM;
    int h  = r / INPUT_DIM;                          // which half of the 8 batches
    int i  = r - h * INPUT_DIM;

    const float* xr = x + ((size_t)bg * BT + h * 4) * INPUT_DIM + i;
    __half2 a = __floats2half2_rn(xr[0],             xr[INPUT_DIM]);
    __half2 b = __floats2half2_rn(xr[2 * INPUT_DIM], xr[3 * INPUT_DIM]);
    uint2 v;
    v.x = *reinterpret_cast<unsigned*>(&a);
    v.y = *reinterpret_cast<unsigned*>(&b);
    reinterpret_cast<uint2*>(g_xprep)[(size_t)(bg * INPUT_DIM + i) * 2 + h] = v;
}

// ---- pre-pass 2: pack idx(u16)+w(fp16) and transpose to [s4][d] ----
__global__ void prep_pack(const int* __restrict__ idx, const float* __restrict__ sw)
{
    int t  = blockIdx.x * blockDim.x + threadIdx.x;  // 0 .. NUM_DEND*8-1
    int d  = t >> 3;
    int s4 = t & 7;
    const int4   i4 = reinterpret_cast<const int4*>(idx)[t];    // coalesced
    const float4 w4 = reinterpret_cast<const float4*>(sw)[t];   // coalesced
    uint4 p;
    p.x = (unsigned)i4.x | ((unsigned)__half_as_ushort(__float2half_rn(w4.x)) << 16);
    p.y = (unsigned)i4.y | ((unsigned)__half_as_ushort(__float2half_rn(w4.y)) << 16);
    p.z = (unsigned)i4.z | ((unsigned)__half_as_ushort(__float2half_rn(w4.z)) << 16);
    p.w = (unsigned)i4.w | ((unsigned)__half_as_ushort(__float2half_rn(w4.w)) << 16);
    g_pk[s4 * NUM_DEND + d] = p;
}

// ---- main kernel ----
__global__ __launch_bounds__(NTHREADS, 2)
void dend_kernel(const float* __restrict__ sb,
                 const float* __restrict__ cw,
                 const float* __restrict__ somab,
                 float* __restrict__ soma_out,
                 float* __restrict__ dend_out)
{
    extern __shared__ uint4 xs[];   // [INPUT_DIM] = 64 KB

    const int bg  = blockIdx.y;
    const int b0  = bg * BT;
    const int d0  = blockIdx.x * DT;
    const int tid = threadIdx.x;

    // Stage packed x group (coalesced LDG.128 + STS.128)
    const uint4* xp = g_xprep + (size_t)bg * INPUT_DIM;
    for (int i = tid; i < INPUT_DIM; i += NTHREADS)
        xs[i] = xp[i];
    __syncthreads();

    const int d = d0 + tid;

    float acc0 = 0.f, acc1 = 0.f, acc2 = 0.f, acc3 = 0.f;
    float acc4 = 0.f, acc5 = 0.f, acc6 = 0.f, acc7 = 0.f;

    #pragma unroll
    for (int s4 = 0; s4 < SAMPLE / 4; ++s4) {
        const uint4 pk = g_pk[s4 * NUM_DEND + d];   // coalesced, 4 samples

        #pragma unroll
        for (int q = 0; q < 4; ++q) {
            const unsigned u = (q == 0) ? pk.x : (q == 1) ? pk.y : (q == 2) ? pk.z : pk.w;
            const int   ix = (int)(u & 0xFFFFu);
            const float w  = __half2float(__ushort_as_half((unsigned short)(u >> 16)));
            const uint4 raw = xs[ix];
            float2 f0 = __half22float2(*reinterpret_cast<const __half2*>(&raw.x));
            float2 f1 = __half22float2(*reinterpret_cast<const __half2*>(&raw.y));
            float2 f2 = __half22float2(*reinterpret_cast<const __half2*>(&raw.z));
            float2 f3 = __half22float2(*reinterpret_cast<const __half2*>(&raw.w));
            acc0 = fmaf(w, f0.x, acc0); acc1 = fmaf(w, f0.y, acc1);
            acc2 = fmaf(w, f1.x, acc2); acc3 = fmaf(w, f1.y, acc3);
            acc4 = fmaf(w, f2.x, acc4); acc5 = fmaf(w, f2.y, acc5);
            acc6 = fmaf(w, f3.x, acc6); acc7 = fmaf(w, f3.y, acc7);
        }
    }

    const float bias = sb[d];
    const float cwv  = cw[d];   // cable_weights flattened [soma][branch] == index d

    float sv[BT];
    float accs[BT] = {acc0, acc1, acc2, acc3, acc4, acc5, acc6, acc7};
    #pragma unroll
    for (int j = 0; j < BT; ++j) {
        float p = accs[j] + bias;
        float a = p >= 0.f ? p : NEG * p;
        dend_out[(size_t)(b0 + j) * NUM_DEND + d] = a;
        sv[j] = a * cwv;
    }

    // Segmented reduction over 16 branches (16 consecutive lanes)
    #pragma unroll
    for (int off = 8; off >= 1; off >>= 1) {
        #pragma unroll
        for (int j = 0; j < BT; ++j)
            sv[j] += __shfl_xor_sync(0xffffffffu, sv[j], off);
    }

    if ((tid & (BRANCH - 1)) == 0) {
        const int n  = d >> 4;
        const float nb = somab[n];
        #pragma unroll
        for (int j = 0; j < BT; ++j) {
            float p = sv[j] + nb;
            soma_out[(size_t)(b0 + j) * SOMA + n] = p >= 0.f ? p : NEG * p;
        }
    }
}

extern "C" void kernel_launch(void* const* d_in, const int* in_sizes, int n_in,
                              void* d_out, int out_size)
{
    const float* x     = (const float*)d_in[0];
    const int*   idx   = (const int*)  d_in[1];
    const float* sw    = (const float*)d_in[2];
    const float* sb    = (const float*)d_in[3];
    const float* cw    = (const float*)d_in[4];
    const float* somab = (const float*)d_in[5];

    float* out      = (float*)d_out;
    float* soma_out = out;                          // [256, 2048]
    float* dend_out = out + (size_t)BATCH * SOMA;   // [256, 32768]

    prep_x   <<<(NBG * 2 * INPUT_DIM) / 256, 256>>>(x);
    prep_pack<<<(NUM_DEND * 8) / 256, 256>>>(idx, sw);

    const size_t smem = INPUT_DIM * sizeof(uint4);  // 64 KB
    cudaFuncSetAttribute(dend_kernel, cudaFuncAttributeMaxDynamicSharedMemorySize, (int)smem);

    dim3 grid(NUM_DEND / DT, BATCH / BT);
    dend_kernel<<<grid, NTHREADS, smem>>>(sb, cw, somab, soma_out, dend_out);
}

// round 6
// speedup vs baseline: 3.4983x; 1.0700x over previous
#include <cuda_runtime.h>
#include <cuda_fp16.h>

#define BATCH      256
#define INPUT_DIM  4096
#define SOMA       2048
#define BRANCH     16
#define NUM_DEND   (SOMA * BRANCH)   // 32768
#define SAMPLE     32
#define NEG        0.1f

#define BT         8                 // batches per block (4x half2 = 16B per x element)
#define NBG        (BATCH / BT)      // 32 batch groups
#define DT         512
#define NTHREADS   512

#define PREP_THREADS 256

// Scratch (allocation-free rule: __device__ globals)
__device__ uint4  g_pk[(SAMPLE/4) * NUM_DEND];     // [s4][d]: 4x {idx:u16, w:fp16}, 4 MB
__device__ uint4  g_xprep[NBG * INPUT_DIM];        // [bg][i]: 8 batches as 4x half2, 2 MB

// ---- pre-pass 1: pack x into batch-interleaved fp16 ----
__global__ void prep_x(const float* __restrict__ x)
{
    int t  = blockIdx.x * blockDim.x + threadIdx.x;  // 0 .. NBG*2*INPUT_DIM-1
    int bg = t / (2 * INPUT_DIM);
    int r  = t - bg * 2 * INPUT_DIM;
    int h  = r / INPUT_DIM;                          // which half of the 8 batches
    int i  = r - h * INPUT_DIM;

    const float* xr = x + ((size_t)bg * BT + h * 4) * INPUT_DIM + i;
    __half2 a = __floats2half2_rn(xr[0],             xr[INPUT_DIM]);
    __half2 b = __floats2half2_rn(xr[2 * INPUT_DIM], xr[3 * INPUT_DIM]);
    uint2 v;
    v.x = *reinterpret_cast<unsigned*>(&a);
    v.y = *reinterpret_cast<unsigned*>(&b);
    reinterpret_cast<uint2*>(g_xprep)[(size_t)(bg * INPUT_DIM + i) * 2 + h] = v;
}

// ---- pre-pass 2: pack idx(u16)+w(fp16), counting-sort by bank class (ix&7),
//      rotate by 4*(d&7), transpose to [s4][d] ----
__global__ void prep_pack(const int* __restrict__ idx, const float* __restrict__ sw)
{
    __shared__ unsigned buf[SAMPLE * PREP_THREADS];  // 32 KB, [pos][tid]

    const int tid = threadIdx.x;
    const int d   = blockIdx.x * PREP_THREADS + tid;

    const int4*   ir = reinterpret_cast<const int4*>(idx) + (size_t)d * (SAMPLE/4);
    const float4* wr = reinterpret_cast<const float4*>(sw) + (size_t)d * (SAMPLE/4);

    // Pass 1: class histogram, counts packed as 8 bytes in a u64
    unsigned long long cnt = 0ull;
    #pragma unroll
    for (int s4 = 0; s4 < SAMPLE/4; ++s4) {
        const int4 i4 = ir[s4];
        cnt += 1ull << (8 * (i4.x & 7));
        cnt += 1ull << (8 * (i4.y & 7));
        cnt += 1ull << (8 * (i4.z & 7));
        cnt += 1ull << (8 * (i4.w & 7));
    }
    // Exclusive prefix over the 8 byte-counters: result byte c = sum of cnt
    // bytes < c. Multiplier sums cnt<<8k for k=1..7; all byte sums <= 32, so
    // no cross-byte carries.
    unsigned long long cursor = cnt * 0x0101010101010100ull;

    // Pass 2: place packed {idx,w} at sorted position
    #pragma unroll
    for (int s4 = 0; s4 < SAMPLE/4; ++s4) {
        const int4   i4 = ir[s4];
        const float4 w4 = wr[s4];
        #pragma unroll
        for (int q = 0; q < 4; ++q) {
            const int   ix = (q == 0) ? i4.x : (q == 1) ? i4.y : (q == 2) ? i4.z : i4.w;
            const float w  = (q == 0) ? w4.x : (q == 1) ? w4.y : (q == 2) ? w4.z : w4.w;
            const int c   = ix & 7;
            const int pos = (int)((cursor >> (8 * c)) & 0xff);
            cursor += 1ull << (8 * c);
            buf[pos * PREP_THREADS + tid] =
                (unsigned)ix | ((unsigned)__half_as_ushort(__float2half_rn(w)) << 16);
        }
    }

    // Output with per-lane rotation so quarter-warp classes are staggered
    const int rot = 4 * (d & 7);
    #pragma unroll
    for (int s4 = 0; s4 < SAMPLE/4; ++s4) {
        uint4 p;
        p.x = buf[(((4*s4 + 0) + rot) & 31) * PREP_THREADS + tid];
        p.y = buf[(((4*s4 + 1) + rot) & 31) * PREP_THREADS + tid];
        p.z = buf[(((4*s4 + 2) + rot) & 31) * PREP_THREADS + tid];
        p.w = buf[(((4*s4 + 3) + rot) & 31) * PREP_THREADS + tid];
        g_pk[s4 * NUM_DEND + d] = p;
    }
}

// ---- main kernel ----
__global__ __launch_bounds__(NTHREADS, 2)
void dend_kernel(const float* __restrict__ sb,
                 const float* __restrict__ cw,
                 const float* __restrict__ somab,
                 float* __restrict__ soma_out,
                 float* __restrict__ dend_out)
{
    extern __shared__ uint4 xs[];   // [INPUT_DIM] = 64 KB

    const int bg  = blockIdx.y;
    const int b0  = bg * BT;
    const int d0  = blockIdx.x * DT;
    const int tid = threadIdx.x;

    const uint4* xp = g_xprep + (size_t)bg * INPUT_DIM;
    for (int i = tid; i < INPUT_DIM; i += NTHREADS)
        xs[i] = xp[i];
    __syncthreads();

    const int d = d0 + tid;

    float acc0 = 0.f, acc1 = 0.f, acc2 = 0.f, acc3 = 0.f;
    float acc4 = 0.f, acc5 = 0.f, acc6 = 0.f, acc7 = 0.f;

    #pragma unroll
    for (int s4 = 0; s4 < SAMPLE / 4; ++s4) {
        const uint4 pk = g_pk[s4 * NUM_DEND + d];   // coalesced, 4 samples

        #pragma unroll
        for (int q = 0; q < 4; ++q) {
            const unsigned u = (q == 0) ? pk.x : (q == 1) ? pk.y : (q == 2) ? pk.z : pk.w;
            const int   ix = (int)(u & 0xFFFFu);
            const float w  = __half2float(__ushort_as_half((unsigned short)(u >> 16)));
            const uint4 raw = xs[ix];
            float2 f0 = __half22float2(*reinterpret_cast<const __half2*>(&raw.x));
            float2 f1 = __half22float2(*reinterpret_cast<const __half2*>(&raw.y));
            float2 f2 = __half22float2(*reinterpret_cast<const __half2*>(&raw.z));
            float2 f3 = __half22float2(*reinterpret_cast<const __half2*>(&raw.w));
            acc0 = fmaf(w, f0.x, acc0); acc1 = fmaf(w, f0.y, acc1);
            acc2 = fmaf(w, f1.x, acc2); acc3 = fmaf(w, f1.y, acc3);
            acc4 = fmaf(w, f2.x, acc4); acc5 = fmaf(w, f2.y, acc5);
            acc6 = fmaf(w, f3.x, acc6); acc7 = fmaf(w, f3.y, acc7);
        }
    }

    const float bias = sb[d];
    const float cwv  = cw[d];   // cable_weights flattened [soma][branch] == index d

    float sv[BT];
    float accs[BT] = {acc0, acc1, acc2, acc3, acc4, acc5, acc6, acc7};
    #pragma unroll
    for (int j = 0; j < BT; ++j) {
        float p = accs[j] + bias;
        float a = p >= 0.f ? p : NEG * p;
        dend_out[(size_t)(b0 + j) * NUM_DEND + d] = a;
        sv[j] = a * cwv;
    }

    #pragma unroll
    for (int off = 8; off >= 1; off >>= 1) {
        #pragma unroll
        for (int j = 0; j < BT; ++j)
            sv[j] += __shfl_xor_sync(0xffffffffu, sv[j], off);
    }

    if ((tid & (BRANCH - 1)) == 0) {
        const int n  = d >> 4;
        const float nb = somab[n];
        #pragma unroll
        for (int j = 0; j < BT; ++j) {
            float p = sv[j] + nb;
            soma_out[(size_t)(b0 + j) * SOMA + n] = p >= 0.f ? p : NEG * p;
        }
    }
}

extern "C" void kernel_launch(void* const* d_in, const int* in_sizes, int n_in,
                              void* d_out, int out_size)
{
    const float* x     = (const float*)d_in[0];
    const int*   idx   = (const int*)  d_in[1];
    const float* sw    = (const float*)d_in[2];
    const float* sb    = (const float*)d_in[3];
    const float* cw    = (const float*)d_in[4];
    const float* somab = (const float*)d_in[5];

    float* out      = (float*)d_out;
    float* soma_out = out;                          // [256, 2048]
    float* dend_out = out + (size_t)BATCH * SOMA;   // [256, 32768]

    prep_x   <<<(NBG * 2 * INPUT_DIM) / 256, 256>>>(x);
    prep_pack<<<NUM_DEND / PREP_THREADS, PREP_THREADS>>>(idx, sw);

    const size_t smem = INPUT_DIM * sizeof(uint4);  // 64 KB
    cudaFuncSetAttribute(dend_kernel, cudaFuncAttributeMaxDynamicSharedMemorySize, (int)smem);

    dim3 grid(NUM_DEND / DT, BATCH / BT);
    dend_kernel<<<grid, NTHREADS, smem>>>(sb, cw, somab, soma_out, dend_out);
}